// round 6
// baseline (speedup 1.0000x reference)
#include <cuda_runtime.h>
#include <cuda_fp16.h>
#include <mma.h>
#include <cstdint>
#include <cstddef>

using namespace nvcuda;

#define NDIM  512
#define BATCH 65536

// Scratch (__device__ globals: allocation-free rule)
__device__ float  g_Wpart[16 * NDIM * NDIM];   // per-(i,j-quarter) partials
__device__ __half g_Wt [NDIM * NDIM];          // W^T  fp16 [n][k]
__device__ __half g_W2t[NDIM * NDIM];          // W2^T fp16 [n][k]

__device__ __forceinline__ uint32_t pack_h2(__half a, __half b) {
    return (uint32_t)__half_as_ushort(a) | ((uint32_t)__half_as_ushort(b) << 16);
}
__device__ __forceinline__ uint32_t smem_u32(const void* p) {
    uint32_t a;
    asm("{ .reg .u64 t; cvta.to.shared.u64 t, %1; cvt.u32.u64 %0, t; }" : "=r"(a) : "l"(p));
    return a;
}
__device__ __forceinline__ void cp_async16(uint32_t dst, const void* src) {
    asm volatile("cp.async.cg.shared.global [%0], [%1], 16;" :: "r"(dst), "l"(src));
}
#define CP_COMMIT() asm volatile("cp.async.commit_group;" ::: "memory")
#define CP_WAIT(n)  asm volatile("cp.async.wait_group %0;" :: "n"(n) : "memory")

// ---------------- Kernel 1: Krylov partial W (split by i and j-quarter) ----------------
// W[a,b] = sum_i sum_j ge_i[512+a-j] * hs_i[b+j]
__global__ __launch_bounds__(256)
void krylov_part(const float* __restrict__ G, const float* __restrict__ H,
                 float* __restrict__ Wp) {
    __shared__ float ge[1024], hs[1024];
    const int tid = threadIdx.x;
    const int i  = blockIdx.z & 3;
    const int j0 = (blockIdx.z >> 2) * 128;
    for (int k = tid; k < 1024; k += 256) {
        ge[k] = G[(k & 511) * 4 + i];
        hs[k] = (k < 512) ? H[k * 4 + i] : -H[(k - 512) * 4 + i];
    }
    __syncthreads();
    const int a0 = blockIdx.y * 64 + (tid >> 4) * 4;
    const int b0 = blockIdx.x * 64 + (tid & 15) * 4;
    float acc[4][4] = {};
    float ga[4], hb[4];
#pragma unroll
    for (int d = 0; d < 4; ++d) ga[d] = ge[512 + a0 + d - j0];
#pragma unroll
    for (int e = 0; e < 4; ++e) hb[e] = hs[b0 + e + j0];
#pragma unroll 4
    for (int j = j0; j < j0 + 128; ++j) {
#pragma unroll
        for (int d = 0; d < 4; ++d)
#pragma unroll
            for (int e = 0; e < 4; ++e)
                acc[d][e] = fmaf(ga[d], hb[e], acc[d][e]);
        ga[3] = ga[2]; ga[2] = ga[1]; ga[1] = ga[0];
        ga[0] = ge[512 + a0 - (j + 1)];
        hb[0] = hb[1]; hb[1] = hb[2]; hb[2] = hb[3];
        hb[3] = hs[b0 + 3 + (j + 1)];
    }
    float* Ws = Wp + (size_t)blockIdx.z * NDIM * NDIM;
#pragma unroll
    for (int d = 0; d < 4; ++d)
#pragma unroll
        for (int e = 0; e < 4; ++e)
            Ws[(a0 + d) * NDIM + (b0 + e)] = acc[d][e];
}

// -------- Kernel 2a: Wt[n][k] = fp16(sum_z Wpart[z][k][n]) --------
__global__ __launch_bounds__(256)
void pack_w(const float* __restrict__ Wp, __half* __restrict__ Wt) {
    __shared__ float t[32][33];
    const int bx = blockIdx.x * 32, by = blockIdx.y * 32, tx = threadIdx.x;
    for (int r = threadIdx.y; r < 32; r += 8) {
        size_t o = (size_t)(bx + r) * NDIM + by + tx;
        float s = 0.f;
#pragma unroll
        for (int z = 0; z < 16; ++z) s += Wp[o + (size_t)z * NDIM * NDIM];
        t[r][tx] = s;
    }
    __syncthreads();
    for (int r = threadIdx.y; r < 32; r += 8)
        Wt[(size_t)(by + r) * NDIM + bx + tx] = __float2half_rn(t[tx][r]);
}

// -------- Kernel 2b: W2t[n][k] = fp16(W2[k][n]) --------
__global__ __launch_bounds__(256)
void pack_w2(const float* __restrict__ W2, __half* __restrict__ W2t) {
    __shared__ float t[32][33];
    const int bx = blockIdx.x * 32, by = blockIdx.y * 32, tx = threadIdx.x;
    for (int r = threadIdx.y; r < 32; r += 8)
        t[r][tx] = W2[(size_t)(bx + r) * NDIM + by + tx];
    __syncthreads();
    for (int r = threadIdx.y; r < 32; r += 8)
        W2t[(size_t)(by + r) * NDIM + bx + tx] = __float2half_rn(t[tx][r]);
}

// ---------------- Kernel 3: fused 2-stage MLP, CTA tile 64 x 512 ----------------
// SMEM map (bytes):
//  [0, 66560)          h tile: 64 x 520 halves (LDH=520)
//  [66560, 232448)     2 stage buffers: A (64x72 halves = 9216) + B (512x72 = 73728)
//                      (also reused as fp32 epilogue scratch: 8 warps x 64x68 f32)
#define LDAB   72
#define LDH    520
#define SH_A(b) (66560u + (b) * 82944u)
#define SH_B(b) (66560u + (b) * 82944u + 9216u)
#define SH_SCR  66560u
#define SMEM_SZ 232448u

__global__ __launch_bounds__(256, 1)
void fused_mlp(const float* __restrict__ x, const __half* __restrict__ Wt,
               const float* __restrict__ b1, const __half* __restrict__ W2t,
               const float* __restrict__ b2, float* __restrict__ out) {
    extern __shared__ char smem[];
    const uint32_t sb = smem_u32(smem);
    __half* smh = (__half*)smem;
    const int tid = threadIdx.x;
    const int w = tid >> 5;                 // warp 0..7, owns n in [w*64, w*64+64)
    const int m0 = blockIdx.x * 64;

    wmma::fragment<wmma::accumulator, 16, 16, 16, float> acc[4][4];

    // ---- A prefetch (x fp32) state ----
    const int arow = tid >> 2;              // 0..63
    const int afq  = tid & 3;               // 4 float4-groups per row
    float4 pa[4];
    auto prefA = [&](int c) {
        const float4* xp = (const float4*)(x + (size_t)(m0 + arow) * NDIM + c * 64 + afq * 16);
#pragma unroll
        for (int i = 0; i < 4; ++i) pa[i] = xp[i];
    };
    auto storeA = [&](int b) {
        uint32_t pk[8];
#pragma unroll
        for (int i = 0; i < 4; ++i) {
            pk[2 * i]     = pack_h2(__float2half_rn(pa[i].x), __float2half_rn(pa[i].y));
            pk[2 * i + 1] = pack_h2(__float2half_rn(pa[i].z), __float2half_rn(pa[i].w));
        }
        uint32_t dst = sb + SH_A(b) + (uint32_t)arow * (LDAB * 2) + afq * 32;
        *(uint4*)(smem + (dst - sb))      = make_uint4(pk[0], pk[1], pk[2], pk[3]);
        *(uint4*)(smem + (dst - sb) + 16) = make_uint4(pk[4], pk[5], pk[6], pk[7]);
    };
    // ---- B loader: 512 rows x 64 halves per chunk via cp.async ----
    auto issueB = [&](const __half* src, int c, int b) {
#pragma unroll
        for (int k = 0; k < 16; ++k) {
            int s = tid + k * 256;
            int rn = s >> 3, sg = s & 7;
            cp_async16(sb + SH_B(b) + (uint32_t)rn * (LDAB * 2) + sg * 16,
                       src + (size_t)rn * NDIM + c * 64 + sg * 8);
        }
        CP_COMMIT();
    };
    // ---- MMA on one chunk: A from (Ap, lda), B from stage buffer b ----
    auto mma_chunk = [&](const __half* Ap, int lda, int b) {
        const __half* Bp = smh + SH_B(b) / 2;
#pragma unroll
        for (int kk = 0; kk < 4; ++kk) {
            wmma::fragment<wmma::matrix_a, 16, 16, 16, __half, wmma::row_major> af[4];
            wmma::fragment<wmma::matrix_b, 16, 16, 16, __half, wmma::col_major> bf[4];
#pragma unroll
            for (int i = 0; i < 4; ++i)
                wmma::load_matrix_sync(af[i], Ap + (i * 16) * lda + kk * 16, lda);
#pragma unroll
            for (int j = 0; j < 4; ++j)
                wmma::load_matrix_sync(bf[j], Bp + (w * 64 + j * 16) * LDAB + kk * 16, LDAB);
#pragma unroll
            for (int i = 0; i < 4; ++i)
#pragma unroll
                for (int j = 0; j < 4; ++j)
                    wmma::mma_sync(acc[i][j], af[i], bf[j], acc[i][j]);
        }
    };
    // ---- dump accs to fp32 scratch (per-warp 64x68 tile) ----
    auto dump = [&]() {
        float* scr = (float*)(smem + SH_SCR) + w * 4352;
#pragma unroll
        for (int i = 0; i < 4; ++i)
#pragma unroll
            for (int j = 0; j < 4; ++j)
                wmma::store_matrix_sync(scr + (i * 16) * 68 + j * 16, acc[i][j], 68,
                                        wmma::mem_row_major);
    };

    // ================= STAGE 1: h = relu(x @ W + b1) =================
#pragma unroll
    for (int i = 0; i < 4; ++i)
#pragma unroll
        for (int j = 0; j < 4; ++j)
            wmma::fill_fragment(acc[i][j], 0.f);

    prefA(0);
    issueB(Wt, 0, 0);
    for (int c = 0; c < 8; ++c) {
        const int b = c & 1;
        storeA(b);
        if (c < 7) issueB(Wt, c + 1, b ^ 1);
        if (c < 7) { CP_WAIT(1); } else { CP_WAIT(0); }
        __syncthreads();
        if (c < 7) prefA(c + 1);
        mma_chunk(smh + SH_A(b) / 2, LDAB, b);
        __syncthreads();
    }
    dump();
    __syncthreads();
    // scratch -> relu+bias -> h (fp16, SMEM resident)
    {
        const int m = tid >> 2, q = tid & 3;
#pragma unroll
        for (int g = 0; g < 16; ++g) {
            int n = q * 128 + g * 8;
            const float* s = (const float*)(smem + SH_SCR) + (n >> 6) * 4352 + m * 68 + (n & 63);
            float4 u = *(const float4*)s;
            float4 v = *(const float4*)(s + 4);
            float4 c0 = *(const float4*)(b1 + n);
            float4 c1 = *(const float4*)(b1 + n + 4);
            float r0 = fmaxf(u.x + c0.x, 0.f), r1 = fmaxf(u.y + c0.y, 0.f);
            float r2 = fmaxf(u.z + c0.z, 0.f), r3 = fmaxf(u.w + c0.w, 0.f);
            float r4 = fmaxf(v.x + c1.x, 0.f), r5 = fmaxf(v.y + c1.y, 0.f);
            float r6 = fmaxf(v.z + c1.z, 0.f), r7 = fmaxf(v.w + c1.w, 0.f);
            uint4 o;
            o.x = pack_h2(__float2half_rn(r0), __float2half_rn(r1));
            o.y = pack_h2(__float2half_rn(r2), __float2half_rn(r3));
            o.z = pack_h2(__float2half_rn(r4), __float2half_rn(r5));
            o.w = pack_h2(__float2half_rn(r6), __float2half_rn(r7));
            *(uint4*)(smh + m * LDH + n) = o;
        }
    }
    __syncthreads();

    // ================= STAGE 2: out = h @ W2 + b2 =================
#pragma unroll
    for (int i = 0; i < 4; ++i)
#pragma unroll
        for (int j = 0; j < 4; ++j)
            wmma::fill_fragment(acc[i][j], 0.f);

    issueB(W2t, 0, 0);
    for (int c = 0; c < 8; ++c) {
        const int b = c & 1;
        if (c < 7) issueB(W2t, c + 1, b ^ 1);
        if (c < 7) { CP_WAIT(1); } else { CP_WAIT(0); }
        __syncthreads();
        mma_chunk(smh + c * 64, LDH, b);
        __syncthreads();
    }
    dump();
    __syncthreads();
    // scratch -> +bias -> out (fp32 global)
    {
        const int m = tid >> 2, q = tid & 3;
        float* orow = out + (size_t)(m0 + m) * NDIM;
#pragma unroll
        for (int g = 0; g < 16; ++g) {
            int n = q * 128 + g * 8;
            const float* s = (const float*)(smem + SH_SCR) + (n >> 6) * 4352 + m * 68 + (n & 63);
            float4 u = *(const float4*)s;
            float4 v = *(const float4*)(s + 4);
            float4 c0 = *(const float4*)(b2 + n);
            float4 c1 = *(const float4*)(b2 + n + 4);
            float4 o0 = make_float4(u.x + c0.x, u.y + c0.y, u.z + c0.z, u.w + c0.w);
            float4 o1 = make_float4(v.x + c1.x, v.y + c1.y, v.z + c1.z, v.w + c1.w);
            *(float4*)(orow + n)     = o0;
            *(float4*)(orow + n + 4) = o1;
        }
    }
}

// ---------------- Launch ----------------
extern "C" void kernel_launch(void* const* d_in, const int* in_sizes, int n_in,
                              void* d_out, int out_size) {
    const float* x  = (const float*)d_in[0];
    const float* G  = (const float*)d_in[1];
    const float* H  = (const float*)d_in[2];
    const float* b1 = (const float*)d_in[3];
    const float* W2 = (const float*)d_in[4];
    const float* b2 = (const float*)d_in[5];
    float* out = (float*)d_out;

    void *pWp, *pWt, *pW2t;
    cudaGetSymbolAddress(&pWp, g_Wpart);
    cudaGetSymbolAddress(&pWt, g_Wt);
    cudaGetSymbolAddress(&pW2t, g_W2t);

    cudaFuncSetAttribute(fused_mlp, cudaFuncAttributeMaxDynamicSharedMemorySize, SMEM_SZ);

    krylov_part<<<dim3(8, 8, 16), 256>>>(G, H, (float*)pWp);
    pack_w<<<dim3(16, 16), dim3(32, 8)>>>((const float*)pWp, (__half*)pWt);
    pack_w2<<<dim3(16, 16), dim3(32, 8)>>>(W2, (__half*)pW2t);

    fused_mlp<<<BATCH / 64, 256, SMEM_SZ>>>(x, (const __half*)pWt, b1,
                                            (const __half*)pW2t, b2, out);
}

// round 7
// speedup vs baseline: 1.1960x; 1.1960x over previous
#include <cuda_runtime.h>
#include <cuda_fp16.h>
#include <mma.h>
#include <cstdint>
#include <cstddef>

using namespace nvcuda;

#define NDIM  512
#define BATCH 65536

// Scratch (__device__ globals: allocation-free rule)
__device__ float  g_Wpart[16 * NDIM * NDIM];   // per-(i,j-quarter) partials
__device__ __half g_Wt [NDIM * NDIM];          // W^T  fp16 [n][k]
__device__ __half g_W2t[NDIM * NDIM];          // W2^T fp16 [n][k]
__device__ __half g_xh[(size_t)BATCH * NDIM];  // x fp16
__device__ __half g_h [(size_t)BATCH * NDIM];  // hidden fp16

__device__ __forceinline__ uint32_t pack_h2(__half a, __half b) {
    return (uint32_t)__half_as_ushort(a) | ((uint32_t)__half_as_ushort(b) << 16);
}
__device__ __forceinline__ uint32_t smem_u32(const void* p) {
    uint32_t a;
    asm("{ .reg .u64 t; cvta.to.shared.u64 t, %1; cvt.u32.u64 %0, t; }" : "=r"(a) : "l"(p));
    return a;
}
__device__ __forceinline__ void cp_async16(uint32_t dst, const void* src) {
    asm volatile("cp.async.cg.shared.global [%0], [%1], 16;" :: "r"(dst), "l"(src));
}
#define CP_COMMIT() asm volatile("cp.async.commit_group;" ::: "memory")
#define CP_WAIT(n)  asm volatile("cp.async.wait_group %0;" :: "n"(n) : "memory")

// ---------------- Kernel 0: x fp32 -> fp16 ----------------
__global__ __launch_bounds__(256)
void xconv(const float* __restrict__ x, __half* __restrict__ xh) {
    size_t i = ((size_t)blockIdx.x * 256 + threadIdx.x) * 8;
    float4 a = *(const float4*)(x + i);
    float4 b = *(const float4*)(x + i + 4);
    uint4 o;
    o.x = pack_h2(__float2half_rn(a.x), __float2half_rn(a.y));
    o.y = pack_h2(__float2half_rn(a.z), __float2half_rn(a.w));
    o.z = pack_h2(__float2half_rn(b.x), __float2half_rn(b.y));
    o.w = pack_h2(__float2half_rn(b.z), __float2half_rn(b.w));
    *(uint4*)(xh + i) = o;
}

// ---------------- Kernel 1: Krylov partial W (split by i and j-quarter) ----------------
// W[a,b] = sum_i sum_j ge_i[512+a-j] * hs_i[b+j]
__global__ __launch_bounds__(256)
void krylov_part(const float* __restrict__ G, const float* __restrict__ H,
                 float* __restrict__ Wp) {
    __shared__ float ge[1024], hs[1024];
    const int tid = threadIdx.x;
    const int i  = blockIdx.z & 3;
    const int j0 = (blockIdx.z >> 2) * 128;
    for (int k = tid; k < 1024; k += 256) {
        ge[k] = G[(k & 511) * 4 + i];
        hs[k] = (k < 512) ? H[k * 4 + i] : -H[(k - 512) * 4 + i];
    }
    __syncthreads();
    const int a0 = blockIdx.y * 64 + (tid >> 4) * 4;
    const int b0 = blockIdx.x * 64 + (tid & 15) * 4;
    float acc[4][4] = {};
    float ga[4], hb[4];
#pragma unroll
    for (int d = 0; d < 4; ++d) ga[d] = ge[512 + a0 + d - j0];
#pragma unroll
    for (int e = 0; e < 4; ++e) hb[e] = hs[b0 + e + j0];
#pragma unroll 4
    for (int j = j0; j < j0 + 128; ++j) {
#pragma unroll
        for (int d = 0; d < 4; ++d)
#pragma unroll
            for (int e = 0; e < 4; ++e)
                acc[d][e] = fmaf(ga[d], hb[e], acc[d][e]);
        ga[3] = ga[2]; ga[2] = ga[1]; ga[1] = ga[0];
        ga[0] = ge[512 + a0 - (j + 1)];
        hb[0] = hb[1]; hb[1] = hb[2]; hb[2] = hb[3];
        hb[3] = hs[b0 + 3 + (j + 1)];
    }
    float* Ws = Wp + (size_t)blockIdx.z * NDIM * NDIM;
#pragma unroll
    for (int d = 0; d < 4; ++d)
#pragma unroll
        for (int e = 0; e < 4; ++e)
            Ws[(a0 + d) * NDIM + (b0 + e)] = acc[d][e];
}

// -------- Kernel 2a: Wt[n][k] = fp16(sum_z Wpart[z][k][n]) --------
__global__ __launch_bounds__(256)
void pack_w(const float* __restrict__ Wp, __half* __restrict__ Wt) {
    __shared__ float t[32][33];
    const int bx = blockIdx.x * 32, by = blockIdx.y * 32, tx = threadIdx.x;
    for (int r = threadIdx.y; r < 32; r += 8) {
        size_t o = (size_t)(bx + r) * NDIM + by + tx;
        float s = 0.f;
#pragma unroll
        for (int z = 0; z < 16; ++z) s += Wp[o + (size_t)z * NDIM * NDIM];
        t[r][tx] = s;
    }
    __syncthreads();
    for (int r = threadIdx.y; r < 32; r += 8)
        Wt[(size_t)(by + r) * NDIM + bx + tx] = __float2half_rn(t[tx][r]);
}

// -------- Kernel 2b: W2t[n][k] = fp16(W2[k][n]) --------
__global__ __launch_bounds__(256)
void pack_w2(const float* __restrict__ W2, __half* __restrict__ W2t) {
    __shared__ float t[32][33];
    const int bx = blockIdx.x * 32, by = blockIdx.y * 32, tx = threadIdx.x;
    for (int r = threadIdx.y; r < 32; r += 8)
        t[r][tx] = W2[(size_t)(bx + r) * NDIM + by + tx];
    __syncthreads();
    for (int r = threadIdx.y; r < 32; r += 8)
        W2t[(size_t)(by + r) * NDIM + bx + tx] = __float2half_rn(t[tx][r]);
}

// ---------------- Kernel 3: wmma GEMM, 128x128 tile, 4 warps (64x64 warp tile) ----------------
// A [m][512] fp16, B [n][512] fp16 (both K-major). K-chunk 64, 3-stage cp.async.
// STAGE 1: C = relu(acc + b1) -> fp16 h.   STAGE 2: C = acc + b2 -> fp32 out.
#define LDAB    72                  // halves per SMEM row (64 + 8 pad)
#define STG_SZ  36864u              // A tile (18432 B) + B tile (18432 B)
#define SBIAS   110592u             // after 3 stages
#define SMEM_SZ 111104u
#define NCHUNK  8

template <int STAGE>
__global__ __launch_bounds__(128, 2)
void gemm_wmma(const __half* __restrict__ Ag, const __half* __restrict__ Bg,
               const float* __restrict__ bias, void* __restrict__ Cg) {
    extern __shared__ char smem[];
    const uint32_t sb = smem_u32(smem);
    __half* smh = (__half*)smem;
    const int tid = threadIdx.x;
    const int w  = tid >> 5;
    const int wm = w >> 1;           // warp row (2): 64 rows each
    const int wn = w & 1;            // warp col (2): 64 cols each
    const int n0 = blockIdx.x * 128;
    const int m0 = blockIdx.y * 128;

    float* bias_s = (float*)(smem + SBIAS);
    if (tid < 128) bias_s[tid] = bias[n0 + tid];

    wmma::fragment<wmma::accumulator, 16, 16, 16, float> acc[4][4];
#pragma unroll
    for (int i = 0; i < 4; ++i)
#pragma unroll
        for (int j = 0; j < 4; ++j)
            wmma::fill_fragment(acc[i][j], 0.f);

    const int rn = tid >> 3;         // 0..15 (x8 iters -> 128 rows)
    const int sg = tid & 7;          // 8 x 16B = 64 halves per row
    const __half* Abase = Ag + (size_t)m0 * NDIM + sg * 8;
    const __half* Bbase = Bg + (size_t)n0 * NDIM + sg * 8;

    auto issue = [&](int c) {
        uint32_t buf = sb + (uint32_t)(c % 3) * STG_SZ;
        const __half* as = Abase + c * 64;
        const __half* bs = Bbase + c * 64;
#pragma unroll
        for (int q = 0; q < 8; ++q)
            cp_async16(buf + (rn + q * 16) * (LDAB * 2) + sg * 16,
                       as + (size_t)(rn + q * 16) * NDIM);
#pragma unroll
        for (int q = 0; q < 8; ++q)
            cp_async16(buf + 18432u + (rn + q * 16) * (LDAB * 2) + sg * 16,
                       bs + (size_t)(rn + q * 16) * NDIM);
        CP_COMMIT();
    };

    issue(0);
    issue(1);

    for (int c = 0; c < NCHUNK; ++c) {
        if (c == NCHUNK - 1) CP_WAIT(0); else CP_WAIT(1);
        __syncthreads();
        if (c + 2 < NCHUNK) issue(c + 2);

        const __half* As = smh + ((c % 3) * STG_SZ) / 2;
        const __half* Bs = As + 18432 / 2;
#pragma unroll
        for (int kk = 0; kk < 4; ++kk) {
            wmma::fragment<wmma::matrix_a, 16, 16, 16, __half, wmma::row_major> af[4];
            wmma::fragment<wmma::matrix_b, 16, 16, 16, __half, wmma::col_major> bf[4];
#pragma unroll
            for (int i = 0; i < 4; ++i)
                wmma::load_matrix_sync(af[i], As + (wm * 64 + i * 16) * LDAB + kk * 16, LDAB);
#pragma unroll
            for (int j = 0; j < 4; ++j)
                wmma::load_matrix_sync(bf[j], Bs + (wn * 64 + j * 16) * LDAB + kk * 16, LDAB);
#pragma unroll
            for (int i = 0; i < 4; ++i)
#pragma unroll
                for (int j = 0; j < 4; ++j)
                    wmma::mma_sync(acc[i][j], af[i], bf[j], acc[i][j]);
        }
        __syncthreads();
    }

    // ---- epilogue: accs -> SMEM fp32 (ld=132), then bias/act/store ----
    float* Cs = (float*)smem;        // 128 x 132 x 4B = 67584 B (reuses stages)
#pragma unroll
    for (int i = 0; i < 4; ++i)
#pragma unroll
        for (int j = 0; j < 4; ++j)
            wmma::store_matrix_sync(Cs + (wm * 64 + i * 16) * 132 + wn * 64 + j * 16,
                                    acc[i][j], 132, wmma::mem_row_major);
    __syncthreads();

    const int r = tid;               // one row per thread
    const float* src = Cs + r * 132;
    if (STAGE == 1) {
        __half* dst = (__half*)Cg + (size_t)(m0 + r) * NDIM + n0;
#pragma unroll
        for (int j = 0; j < 128; j += 8) {
            uint4 o;
            float v0 = fmaxf(src[j+0] + bias_s[j+0], 0.f), v1 = fmaxf(src[j+1] + bias_s[j+1], 0.f);
            float v2 = fmaxf(src[j+2] + bias_s[j+2], 0.f), v3 = fmaxf(src[j+3] + bias_s[j+3], 0.f);
            float v4 = fmaxf(src[j+4] + bias_s[j+4], 0.f), v5 = fmaxf(src[j+5] + bias_s[j+5], 0.f);
            float v6 = fmaxf(src[j+6] + bias_s[j+6], 0.f), v7 = fmaxf(src[j+7] + bias_s[j+7], 0.f);
            o.x = pack_h2(__float2half_rn(v0), __float2half_rn(v1));
            o.y = pack_h2(__float2half_rn(v2), __float2half_rn(v3));
            o.z = pack_h2(__float2half_rn(v4), __float2half_rn(v5));
            o.w = pack_h2(__float2half_rn(v6), __float2half_rn(v7));
            *(uint4*)(dst + j) = o;
        }
    } else {
        float* dst = (float*)Cg + (size_t)(m0 + r) * NDIM + n0;
#pragma unroll
        for (int j = 0; j < 128; j += 4) {
            float4 o;
            o.x = src[j+0] + bias_s[j+0];
            o.y = src[j+1] + bias_s[j+1];
            o.z = src[j+2] + bias_s[j+2];
            o.w = src[j+3] + bias_s[j+3];
            *(float4*)(dst + j) = o;
        }
    }
}

// ---------------- Launch ----------------
extern "C" void kernel_launch(void* const* d_in, const int* in_sizes, int n_in,
                              void* d_out, int out_size) {
    const float* x  = (const float*)d_in[0];
    const float* G  = (const float*)d_in[1];
    const float* H  = (const float*)d_in[2];
    const float* b1 = (const float*)d_in[3];
    const float* W2 = (const float*)d_in[4];
    const float* b2 = (const float*)d_in[5];
    float* out = (float*)d_out;

    void *pWp, *pWt, *pW2t, *pxh, *ph;
    cudaGetSymbolAddress(&pWp, g_Wpart);
    cudaGetSymbolAddress(&pWt, g_Wt);
    cudaGetSymbolAddress(&pW2t, g_W2t);
    cudaGetSymbolAddress(&pxh, g_xh);
    cudaGetSymbolAddress(&ph, g_h);

    cudaFuncSetAttribute(gemm_wmma<1>, cudaFuncAttributeMaxDynamicSharedMemorySize, SMEM_SZ);
    cudaFuncSetAttribute(gemm_wmma<2>, cudaFuncAttributeMaxDynamicSharedMemorySize, SMEM_SZ);

    xconv<<<(BATCH * NDIM) / (256 * 8), 256>>>(x, (__half*)pxh);
    krylov_part<<<dim3(8, 8, 16), 256>>>(G, H, (float*)pWp);
    pack_w<<<dim3(16, 16), dim3(32, 8)>>>((const float*)pWp, (__half*)pWt);
    pack_w2<<<dim3(16, 16), dim3(32, 8)>>>(W2, (__half*)pW2t);

    gemm_wmma<1><<<dim3(4, BATCH / 128), 128, SMEM_SZ>>>((const __half*)pxh, (const __half*)pWt,  b1, ph);
    gemm_wmma<2><<<dim3(4, BATCH / 128), 128, SMEM_SZ>>>((const __half*)ph,  (const __half*)pW2t, b2, out);
}